// round 11
// baseline (speedup 1.0000x reference)
#include <cuda_runtime.h>
#include <cuda_bf16.h>
#include <cstdint>

#define N_TOK 4096
#define D_MODEL 1024

// ---------------------------------------------------------------------------
// Scratch (__device__ globals; no allocations allowed)
// ---------------------------------------------------------------------------
__device__ __nv_bfloat16 g_xh[(size_t)N_TOK * D_MODEL];
__device__ __nv_bfloat16 g_xl[(size_t)N_TOK * D_MODEL];
__device__ __nv_bfloat16 g_w1h[(size_t)D_MODEL * D_MODEL];
__device__ __nv_bfloat16 g_w1l[(size_t)D_MODEL * D_MODEL];
__device__ __nv_bfloat16 g_w2h[(size_t)D_MODEL * D_MODEL];
__device__ __nv_bfloat16 g_w2l[(size_t)D_MODEL * D_MODEL];
__device__ __nv_bfloat16 g_w3h[(size_t)D_MODEL * D_MODEL];
__device__ __nv_bfloat16 g_w3l[(size_t)D_MODEL * D_MODEL];
__device__ __nv_bfloat16 g_qh[(size_t)N_TOK * D_MODEL];
__device__ __nv_bfloat16 g_ql[(size_t)N_TOK * D_MODEL];
__device__ __nv_bfloat16 g_kh[(size_t)N_TOK * D_MODEL];
__device__ __nv_bfloat16 g_kl[(size_t)N_TOK * D_MODEL];
__device__ __nv_bfloat16 g_vh[(size_t)N_TOK * D_MODEL];
__device__ __nv_bfloat16 g_vl[(size_t)N_TOK * D_MODEL];
__device__ float         g_S [(size_t)N_TOK * N_TOK];
__device__ __nv_bfloat16 g_sh[(size_t)N_TOK * N_TOK];
__device__ __nv_bfloat16 g_sl[(size_t)N_TOK * N_TOK];

// ---------------------------------------------------------------------------
// PTX helpers
// ---------------------------------------------------------------------------
__device__ __forceinline__ uint32_t smem_u32(const void* p) {
    return (uint32_t)__cvta_generic_to_shared(p);
}
__device__ __forceinline__ void cp_async16(uint32_t dst, const void* src) {
    asm volatile("cp.async.cg.shared.global [%0], [%1], 16;\n" :: "r"(dst), "l"(src));
}
__device__ __forceinline__ void cp_commit() {
    asm volatile("cp.async.commit_group;\n" ::: "memory");
}
template <int N>
__device__ __forceinline__ void cp_wait() {
    asm volatile("cp.async.wait_group %0;\n" :: "n"(N) : "memory");
}
__device__ __forceinline__ void ldsm_x4(uint32_t& r0, uint32_t& r1, uint32_t& r2, uint32_t& r3,
                                        uint32_t addr) {
    asm volatile("ldmatrix.sync.aligned.m8n8.x4.shared.b16 {%0,%1,%2,%3}, [%4];\n"
                 : "=r"(r0), "=r"(r1), "=r"(r2), "=r"(r3) : "r"(addr));
}
__device__ __forceinline__ void ldsm_x4_t(uint32_t& r0, uint32_t& r1, uint32_t& r2, uint32_t& r3,
                                          uint32_t addr) {
    asm volatile("ldmatrix.sync.aligned.m8n8.x4.trans.shared.b16 {%0,%1,%2,%3}, [%4];\n"
                 : "=r"(r0), "=r"(r1), "=r"(r2), "=r"(r3) : "r"(addr));
}
__device__ __forceinline__ void mma16816(float* c, const uint32_t* a, const uint32_t* b) {
    asm volatile(
        "mma.sync.aligned.m16n8k16.row.col.f32.bf16.bf16.f32 "
        "{%0,%1,%2,%3}, {%4,%5,%6,%7}, {%8,%9}, {%0,%1,%2,%3};\n"
        : "+f"(c[0]), "+f"(c[1]), "+f"(c[2]), "+f"(c[3])
        : "r"(a[0]), "r"(a[1]), "r"(a[2]), "r"(a[3]), "r"(b[0]), "r"(b[1]));
}

// ---------------------------------------------------------------------------
// Split fp32 -> (hi, lo) bf16
// ---------------------------------------------------------------------------
__device__ __forceinline__ void split_body(const float* __restrict__ in,
                                           __nv_bfloat16* __restrict__ hi,
                                           __nv_bfloat16* __restrict__ lo, int i, int n4) {
    if (i >= n4) return;
    float4 v = ((const float4*)in)[i];
    __nv_bfloat16 h0 = __float2bfloat16(v.x);
    __nv_bfloat16 h1 = __float2bfloat16(v.y);
    __nv_bfloat16 h2 = __float2bfloat16(v.z);
    __nv_bfloat16 h3 = __float2bfloat16(v.w);
    __nv_bfloat16 l0 = __float2bfloat16(v.x - __bfloat162float(h0));
    __nv_bfloat16 l1 = __float2bfloat16(v.y - __bfloat162float(h1));
    __nv_bfloat16 l2 = __float2bfloat16(v.z - __bfloat162float(h2));
    __nv_bfloat16 l3 = __float2bfloat16(v.w - __bfloat162float(h3));
    ((__nv_bfloat162*)hi)[2 * i + 0] = __halves2bfloat162(h0, h1);
    ((__nv_bfloat162*)hi)[2 * i + 1] = __halves2bfloat162(h2, h3);
    ((__nv_bfloat162*)lo)[2 * i + 0] = __halves2bfloat162(l0, l1);
    ((__nv_bfloat162*)lo)[2 * i + 1] = __halves2bfloat162(l2, l3);
}

__global__ __launch_bounds__(256)
void split_kernel(const float* __restrict__ in, __nv_bfloat16* __restrict__ hi,
                  __nv_bfloat16* __restrict__ lo, int n4) {
    split_body(in, hi, lo, blockIdx.x * blockDim.x + threadIdx.x, n4);
}

__global__ __launch_bounds__(256)
void split3_kernel(const float* __restrict__ i0, __nv_bfloat16* __restrict__ h0, __nv_bfloat16* __restrict__ l0,
                   const float* __restrict__ i1, __nv_bfloat16* __restrict__ h1, __nv_bfloat16* __restrict__ l1,
                   const float* __restrict__ i2, __nv_bfloat16* __restrict__ h2, __nv_bfloat16* __restrict__ l2,
                   int n4) {
    const int i = blockIdx.x * blockDim.x + threadIdx.x;
    if (blockIdx.y == 0)      split_body(i0, h0, l0, i, n4);
    else if (blockIdx.y == 1) split_body(i1, h1, l1, i, n4);
    else                      split_body(i2, h2, l2, i, n4);
}

// ---------------------------------------------------------------------------
// Split-bf16 tensor-core GEMM (mma.sync).  BK=32, 3-stage cp.async pipeline,
// one __syncthreads per chunk, 2 CTAs/SM.
// Warp term-rotation (3 phases, wid%3): each warp runs a different rotation of
// the per-ks term sequence {hh, hl, lh}, so at any instant ~1/3 of warps are
// in ldsm phase while the rest issue MMAs -> tensor pipe stays fed across
// group boundaries.  (fp32 accumulation reorder only.)
// K-major smem arrays: 128 rows x 64B, XOR-swizzled (g' = g ^ ((r>>1)&3)).
// B [K][N] (trans) array: 32 rows x 272B pitch.
// ---------------------------------------------------------------------------
#define ARR_KMAJ 8192                     // 128 * 64
#define BSZ_TRUE 8192
#define BSZ_FALSE 8704                    // 32 * 272
#define ST_BYTES(BT_) (2 * ARR_KMAJ + 2 * ((BT_) ? BSZ_TRUE : BSZ_FALSE))
#define GM_SMEM(BT_)  (3 * ST_BYTES(BT_))

template <bool BT, bool HAS_BIAS, bool WF32, bool WBF16, bool QKV3>
__global__ __launch_bounds__(256, 2)
void mma_gemm(const __nv_bfloat16* __restrict__ Ah, const __nv_bfloat16* __restrict__ Al,
              const __nv_bfloat16* __restrict__ Bh0, const __nv_bfloat16* __restrict__ Bl0,
              const __nv_bfloat16* __restrict__ Bh1, const __nv_bfloat16* __restrict__ Bl1,
              const __nv_bfloat16* __restrict__ Bh2, const __nv_bfloat16* __restrict__ Bl2,
              const float* __restrict__ bias0, const float* __restrict__ bias1,
              const float* __restrict__ bias2,
              float* __restrict__ Cf,
              __nv_bfloat16* __restrict__ Ch0, __nv_bfloat16* __restrict__ Cl0,
              __nv_bfloat16* __restrict__ Ch1, __nv_bfloat16* __restrict__ Cl1,
              __nv_bfloat16* __restrict__ Ch2, __nv_bfloat16* __restrict__ Cl2,
              int M, int Ncols, int Kdim, float alpha) {
    extern __shared__ __nv_bfloat16 sm[];

    constexpr int BSZ = BT ? BSZ_TRUE : BSZ_FALSE;
    constexpr int STB = 2 * ARR_KMAJ + 2 * BSZ;
    constexpr uint32_t OFF_AL = ARR_KMAJ;
    constexpr uint32_t OFF_BH = 2 * ARR_KMAJ;
    constexpr uint32_t OFF_BL = 2 * ARR_KMAJ + BSZ;

    const int tid  = threadIdx.x;
    const int lane = tid & 31;
    const int wid  = tid >> 5;
    const int wm   = (wid >> 2) * 64;
    const int wn   = (wid & 3) * 32;
    const int bm   = blockIdx.y * 128;
    const int bn   = blockIdx.x * 128;
    const int wph  = wid % 3;            // term-rotation phase

    const __nv_bfloat16* Bh = Bh0;
    const __nv_bfloat16* Bl = Bl0;
    const float* bias = bias0;
    __nv_bfloat16* Ch = Ch0;
    __nv_bfloat16* Cl = Cl0;
    if (QKV3) {
        if (blockIdx.z == 1) { Bh = Bh1; Bl = Bl1; bias = bias1; Ch = Ch1; Cl = Cl1; }
        else if (blockIdx.z == 2) { Bh = Bh2; Bl = Bl2; bias = bias2; Ch = Ch2; Cl = Cl2; }
    }

    float acc[4][4][4];
#pragma unroll
    for (int i = 0; i < 4; i++)
#pragma unroll
        for (int j = 0; j < 4; j++)
#pragma unroll
            for (int k = 0; k < 4; k++) acc[i][j][k] = 0.f;

    const uint32_t smb = smem_u32(&sm[0]);

    // ldsm row bases + swizzle masks (K-major arrays)
    uint32_t rowa[4], swza[4];
#pragma unroll
    for (int mi = 0; mi < 4; mi++) {
        const int r = wm + mi * 16 + (lane & 15);
        rowa[mi] = (uint32_t)(r * 64);
        swza[mi] = (uint32_t)((r >> 1) & 3);
    }
    uint32_t rowb[2], swzb[2], offbt[2];
#pragma unroll
    for (int nb = 0; nb < 2; nb++) {
        if (BT) {
            const int r = wn + nb * 16 + (lane & 15);
            rowb[nb] = (uint32_t)(r * 64);
            swzb[nb] = (uint32_t)((r >> 1) & 3);
        } else {
            offbt[nb] = (uint32_t)((lane & 15) * 272 + (wn + nb * 16 + (lane >> 4) * 8) * 2);
        }
    }

    const int nk = Kdim >> 5;   // BK=32 chunks

    auto load_stage = [&](int st, int kc) {
        const uint32_t base = smb + (uint32_t)st * STB;
        const int k0 = kc * 32;
#pragma unroll
        for (int p = 0; p < 2; p++) {
            const int G = tid * 2 + p;
            {
                const int r = G >> 2, g = G & 3;
                const uint32_t d = (uint32_t)(r * 64 + ((g ^ ((r >> 1) & 3)) * 16));
                const size_t o = (size_t)(bm + r) * Kdim + k0 + g * 8;
                cp_async16(base + d, Ah + o);
                cp_async16(base + OFF_AL + d, Al + o);
            }
            if (BT) {
                const int r = G >> 2, g = G & 3;
                const uint32_t d = (uint32_t)(r * 64 + ((g ^ ((r >> 1) & 3)) * 16));
                const size_t o = (size_t)(bn + r) * Kdim + k0 + g * 8;
                cp_async16(base + OFF_BH + d, Bh + o);
                cp_async16(base + OFF_BL + d, Bl + o);
            } else {
                const int r = G >> 4, c = G & 15;
                const uint32_t d = (uint32_t)(r * 272 + c * 16);
                const size_t o = (size_t)(k0 + r) * Ncols + bn + c * 8;
                cp_async16(base + OFF_BH + d, Bh + o);
                cp_async16(base + OFF_BL + d, Bl + o);
            }
        }
        cp_commit();
    };

    load_stage(0, 0);
    if (nk > 1) load_stage(1, 1);

    // fragment buffers: one A (reloaded per term as needed), two B (Bh, Bl)
    uint32_t fA[4][4], fBH[4][2], fBL[4][2];

    for (int i = 0; i < nk; i++) {
        const int st = i % 3;
        if (i + 1 < nk) cp_wait<1>();
        else            cp_wait<0>();
        __syncthreads();
        if (i + 2 < nk) load_stage((i + 2) % 3, i + 2);

        const uint32_t base = smb + (uint32_t)st * STB;

#pragma unroll
        for (int ks = 0; ks < 2; ks++) {
            const uint32_t gbase = (uint32_t)(ks * 2 + (lane >> 4));  // logical granule 0..3

            auto load_A = [&](uint32_t arrOff) {
#pragma unroll
                for (int mi = 0; mi < 4; mi++) {
                    const uint32_t d = rowa[mi] + ((gbase ^ swza[mi]) * 16);
                    ldsm_x4(fA[mi][0], fA[mi][1], fA[mi][2], fA[mi][3], base + arrOff + d);
                }
            };
            auto load_B = [&](uint32_t arrOff, uint32_t (*fB)[2]) {
#pragma unroll
                for (int nb = 0; nb < 2; nb++) {
                    uint32_t r0, r1, r2, r3;
                    if (BT) {
                        const uint32_t d = rowb[nb] + ((gbase ^ swzb[nb]) * 16);
                        ldsm_x4(r0, r1, r2, r3, base + arrOff + d);
                        fB[2 * nb][0] = r0; fB[2 * nb][1] = r2;
                        fB[2 * nb + 1][0] = r1; fB[2 * nb + 1][1] = r3;
                    } else {
                        const uint32_t d = offbt[nb] + (uint32_t)(ks * 16 * 272);
                        ldsm_x4_t(r0, r1, r2, r3, base + arrOff + d);
                        fB[2 * nb][0] = r0; fB[2 * nb][1] = r1;
                        fB[2 * nb + 1][0] = r2; fB[2 * nb + 1][1] = r3;
                    }
                }
            };
            auto mma_all = [&](uint32_t (*fB)[2]) {
#pragma unroll
                for (int mi = 0; mi < 4; mi++)
#pragma unroll
                    for (int ni = 0; ni < 4; ni++)
                        mma16816(acc[mi][ni], fA[mi], fB[ni]);
            };

            if (wph == 0) {
                // hh -> hl -> lh
                load_A(0);        load_B(OFF_BH, fBH); mma_all(fBH);
                load_B(OFF_BL, fBL);                   mma_all(fBL);
                load_A(OFF_AL);                        mma_all(fBH);
            } else if (wph == 1) {
                // hl -> lh -> hh
                load_A(0);        load_B(OFF_BL, fBL); mma_all(fBL);
                load_A(OFF_AL);   load_B(OFF_BH, fBH); mma_all(fBH);
                load_A(0);                             mma_all(fBH);
            } else {
                // lh -> hh -> hl
                load_A(OFF_AL);   load_B(OFF_BH, fBH); mma_all(fBH);
                load_A(0);                             mma_all(fBH);
                load_B(OFF_BL, fBL);                   mma_all(fBL);
            }
        }
    }

    // ---- epilogue
#pragma unroll
    for (int mi = 0; mi < 4; mi++) {
#pragma unroll
        for (int ni = 0; ni < 4; ni++) {
#pragma unroll
            for (int h = 0; h < 2; h++) {
                const int r = bm + wm + mi * 16 + (lane >> 2) + h * 8;
                const int c = bn + wn + ni * 8 + ((lane & 3) << 1);
                float v0 = acc[mi][ni][2 * h + 0] * alpha;
                float v1 = acc[mi][ni][2 * h + 1] * alpha;
                if (HAS_BIAS) { v0 += bias[c]; v1 += bias[c + 1]; }
                const size_t idx = (size_t)r * Ncols + c;
                if (WF32) {
                    float2 o; o.x = v0; o.y = v1;
                    *(float2*)(Cf + idx) = o;
                }
                if (WBF16) {
                    __nv_bfloat16 h0 = __float2bfloat16(v0);
                    __nv_bfloat16 h1 = __float2bfloat16(v1);
                    __nv_bfloat16 l0 = __float2bfloat16(v0 - __bfloat162float(h0));
                    __nv_bfloat16 l1 = __float2bfloat16(v1 - __bfloat162float(h1));
                    *(__nv_bfloat162*)(Ch + idx) = __halves2bfloat162(h0, h1);
                    *(__nv_bfloat162*)(Cl + idx) = __halves2bfloat162(l0, l1);
                }
            }
        }
    }
}

// ---------------------------------------------------------------------------
// Row softmax over fp32 S; emits bf16 hi/lo of the probabilities.
// ---------------------------------------------------------------------------
__global__ __launch_bounds__(256)
void softmax_split(const float* __restrict__ S, __nv_bfloat16* __restrict__ Sh,
                   __nv_bfloat16* __restrict__ Sl) {
    constexpr int T = 256;
    constexpr int VPT = N_TOK / T;  // 16
    const int row = blockIdx.x;
    const int tid = threadIdx.x;
    const float* p = S + (size_t)row * N_TOK;

    float v[VPT];
    float m = -3.0e38f;
#pragma unroll
    for (int i = 0; i < VPT; i++) {
        v[i] = p[tid + i * T];
        m = fmaxf(m, v[i]);
    }
    __shared__ float red[T];
    red[tid] = m;
    __syncthreads();
    for (int s = T / 2; s > 0; s >>= 1) {
        if (tid < s) red[tid] = fmaxf(red[tid], red[tid + s]);
        __syncthreads();
    }
    m = red[0];
    __syncthreads();

    float sum = 0.f;
#pragma unroll
    for (int i = 0; i < VPT; i++) {
        v[i] = __expf(v[i] - m);
        sum += v[i];
    }
    red[tid] = sum;
    __syncthreads();
    for (int s = T / 2; s > 0; s >>= 1) {
        if (tid < s) red[tid] += red[tid + s];
        __syncthreads();
    }
    const float inv = 1.f / red[0];
#pragma unroll
    for (int i = 0; i < VPT; i++) {
        const float w = v[i] * inv;
        const __nv_bfloat16 h = __float2bfloat16(w);
        const __nv_bfloat16 l = __float2bfloat16(w - __bfloat162float(h));
        Sh[(size_t)row * N_TOK + tid + i * T] = h;
        Sl[(size_t)row * N_TOK + tid + i * T] = l;
    }
}

// ---------------------------------------------------------------------------
// Launch
// ---------------------------------------------------------------------------
extern "C" void kernel_launch(void* const* d_in, const int* in_sizes, int n_in,
                              void* d_out, int out_size) {
    const float* x  = (const float*)d_in[0];
    const float* W1 = (const float*)d_in[1];
    const float* b1 = (const float*)d_in[2];
    const float* W2 = (const float*)d_in[3];
    const float* b2 = (const float*)d_in[4];
    const float* W3 = (const float*)d_in[5];
    const float* b3 = (const float*)d_in[6];
    float* out = (float*)d_out;

    __nv_bfloat16 *xh, *xl, *w1h, *w1l, *w2h, *w2l, *w3h, *w3l;
    __nv_bfloat16 *qh, *ql, *kh, *kl, *vh, *vl, *sh, *sl;
    float* S;
    cudaGetSymbolAddress((void**)&xh, g_xh);   cudaGetSymbolAddress((void**)&xl, g_xl);
    cudaGetSymbolAddress((void**)&w1h, g_w1h); cudaGetSymbolAddress((void**)&w1l, g_w1l);
    cudaGetSymbolAddress((void**)&w2h, g_w2h); cudaGetSymbolAddress((void**)&w2l, g_w2l);
    cudaGetSymbolAddress((void**)&w3h, g_w3h); cudaGetSymbolAddress((void**)&w3l, g_w3l);
    cudaGetSymbolAddress((void**)&qh, g_qh);   cudaGetSymbolAddress((void**)&ql, g_ql);
    cudaGetSymbolAddress((void**)&kh, g_kh);   cudaGetSymbolAddress((void**)&kl, g_kl);
    cudaGetSymbolAddress((void**)&vh, g_vh);   cudaGetSymbolAddress((void**)&vl, g_vl);
    cudaGetSymbolAddress((void**)&sh, g_sh);   cudaGetSymbolAddress((void**)&sl, g_sl);
    cudaGetSymbolAddress((void**)&S, g_S);

    cudaFuncSetAttribute(mma_gemm<true, true, false, true, true>,
                         cudaFuncAttributeMaxDynamicSharedMemorySize, GM_SMEM(true));
    cudaFuncSetAttribute(mma_gemm<true, false, true, false, false>,
                         cudaFuncAttributeMaxDynamicSharedMemorySize, GM_SMEM(true));
    cudaFuncSetAttribute(mma_gemm<false, false, true, false, false>,
                         cudaFuncAttributeMaxDynamicSharedMemorySize, GM_SMEM(false));

    const dim3 blk(256);

    const int nx4 = N_TOK * D_MODEL / 4;
    const int nw4 = D_MODEL * D_MODEL / 4;
    split_kernel<<<(nx4 + 255) / 256, blk>>>(x, xh, xl, nx4);
    split3_kernel<<<dim3((nw4 + 255) / 256, 3), blk>>>(
        W1, w1h, w1l, W2, w2h, w2l, W3, w3h, w3l, nw4);

    const dim3 grid_qkv(D_MODEL / 128, N_TOK / 128, 3);  // (8, 32, 3)
    const dim3 grid_attn(N_TOK / 128, N_TOK / 128);      // (32, 32)
    const dim3 grid_pv(D_MODEL / 128, N_TOK / 128);      // (8, 32)

    // merged Q/K/V projections (bf16 hi/lo out, +bias)
    mma_gemm<true, true, false, true, true><<<grid_qkv, blk, GM_SMEM(true)>>>(
        xh, xl, w1h, w1l, w2h, w2l, w3h, w3l, b1, b2, b3,
        nullptr, qh, ql, kh, kl, vh, vl, N_TOK, D_MODEL, D_MODEL, 1.f);

    // S = scale * K @ Q^T  (fp32 out)
    const float scale = rsqrtf((float)D_MODEL);
    mma_gemm<true, false, true, false, false><<<grid_attn, blk, GM_SMEM(true)>>>(
        kh, kl, qh, ql, nullptr, nullptr, nullptr, nullptr, nullptr, nullptr, nullptr,
        S, nullptr, nullptr, nullptr, nullptr, nullptr, nullptr,
        N_TOK, N_TOK, D_MODEL, scale);

    // softmax rows -> bf16 hi/lo probabilities
    softmax_split<<<N_TOK, blk>>>(S, sh, sl);

    // out = P @ V (fp32 out)
    mma_gemm<false, false, true, false, false><<<grid_pv, blk, GM_SMEM(false)>>>(
        sh, sl, vh, vl, nullptr, nullptr, nullptr, nullptr, nullptr, nullptr, nullptr,
        out, nullptr, nullptr, nullptr, nullptr, nullptr, nullptr,
        N_TOK, D_MODEL, N_TOK, 1.f);
}

// round 15
// speedup vs baseline: 1.0272x; 1.0272x over previous
#include <cuda_runtime.h>
#include <cuda_bf16.h>
#include <cstdint>

#define N_TOK 4096
#define D_MODEL 1024

// ---------------------------------------------------------------------------
// Scratch (__device__ globals; no allocations allowed)
// ---------------------------------------------------------------------------
__device__ __nv_bfloat16 g_xh[(size_t)N_TOK * D_MODEL];
__device__ __nv_bfloat16 g_xl[(size_t)N_TOK * D_MODEL];
__device__ __nv_bfloat16 g_w1h[(size_t)D_MODEL * D_MODEL];
__device__ __nv_bfloat16 g_w1l[(size_t)D_MODEL * D_MODEL];
__device__ __nv_bfloat16 g_w2h[(size_t)D_MODEL * D_MODEL];
__device__ __nv_bfloat16 g_w2l[(size_t)D_MODEL * D_MODEL];
__device__ __nv_bfloat16 g_w3h[(size_t)D_MODEL * D_MODEL];
__device__ __nv_bfloat16 g_w3l[(size_t)D_MODEL * D_MODEL];
__device__ __nv_bfloat16 g_qh[(size_t)N_TOK * D_MODEL];
__device__ __nv_bfloat16 g_ql[(size_t)N_TOK * D_MODEL];
__device__ __nv_bfloat16 g_kh[(size_t)N_TOK * D_MODEL];
__device__ __nv_bfloat16 g_kl[(size_t)N_TOK * D_MODEL];
__device__ __nv_bfloat16 g_vh[(size_t)N_TOK * D_MODEL];
__device__ __nv_bfloat16 g_vl[(size_t)N_TOK * D_MODEL];
__device__ float         g_S [(size_t)N_TOK * N_TOK];
__device__ __nv_bfloat16 g_sh[(size_t)N_TOK * N_TOK];
__device__ __nv_bfloat16 g_sl[(size_t)N_TOK * N_TOK];

// ---------------------------------------------------------------------------
// PTX helpers
// ---------------------------------------------------------------------------
__device__ __forceinline__ uint32_t smem_u32(const void* p) {
    return (uint32_t)__cvta_generic_to_shared(p);
}
__device__ __forceinline__ void cp_async16(uint32_t dst, const void* src) {
    asm volatile("cp.async.cg.shared.global [%0], [%1], 16;\n" :: "r"(dst), "l"(src));
}
__device__ __forceinline__ void mbar_init(uint32_t addr, uint32_t cnt) {
    asm volatile("mbarrier.init.shared.b64 [%0], %1;" :: "r"(addr), "r"(cnt) : "memory");
}
__device__ __forceinline__ void mbar_arrive(uint32_t addr) {
    asm volatile("mbarrier.arrive.shared.b64 _, [%0];" :: "r"(addr) : "memory");
}
// .noinc is load-bearing: the default form increments the pending count before
// decrementing on completion (net zero vs the expected 256 arrivals -> deadlock).
__device__ __forceinline__ void cpasync_mbar_arrive_noinc(uint32_t addr) {
    asm volatile("cp.async.mbarrier.arrive.noinc.shared.b64 [%0];" :: "r"(addr) : "memory");
}
__device__ __forceinline__ void mbar_wait(uint32_t addr, uint32_t parity) {
    asm volatile(
        "{\n\t.reg .pred P1;\n\t"
        "WAIT_LOOP_%=:\n\t"
        "mbarrier.try_wait.parity.acquire.cta.shared::cta.b64 P1, [%0], %1, 0x989680;\n\t"
        "@P1 bra.uni WAIT_DONE_%=;\n\t"
        "bra.uni WAIT_LOOP_%=;\n\t"
        "WAIT_DONE_%=:\n\t}"
        :: "r"(addr), "r"(parity) : "memory");
}
__device__ __forceinline__ void ldsm_x4(uint32_t& r0, uint32_t& r1, uint32_t& r2, uint32_t& r3,
                                        uint32_t addr) {
    asm volatile("ldmatrix.sync.aligned.m8n8.x4.shared.b16 {%0,%1,%2,%3}, [%4];\n"
                 : "=r"(r0), "=r"(r1), "=r"(r2), "=r"(r3) : "r"(addr));
}
__device__ __forceinline__ void ldsm_x4_t(uint32_t& r0, uint32_t& r1, uint32_t& r2, uint32_t& r3,
                                          uint32_t addr) {
    asm volatile("ldmatrix.sync.aligned.m8n8.x4.trans.shared.b16 {%0,%1,%2,%3}, [%4];\n"
                 : "=r"(r0), "=r"(r1), "=r"(r2), "=r"(r3) : "r"(addr));
}
__device__ __forceinline__ void mma16816(float* c, const uint32_t* a, const uint32_t* b) {
    asm volatile(
        "mma.sync.aligned.m16n8k16.row.col.f32.bf16.bf16.f32 "
        "{%0,%1,%2,%3}, {%4,%5,%6,%7}, {%8,%9}, {%0,%1,%2,%3};\n"
        : "+f"(c[0]), "+f"(c[1]), "+f"(c[2]), "+f"(c[3])
        : "r"(a[0]), "r"(a[1]), "r"(a[2]), "r"(a[3]), "r"(b[0]), "r"(b[1]));
}

// ---------------------------------------------------------------------------
// Split fp32 -> (hi, lo) bf16
// ---------------------------------------------------------------------------
__device__ __forceinline__ void split_body(const float* __restrict__ in,
                                           __nv_bfloat16* __restrict__ hi,
                                           __nv_bfloat16* __restrict__ lo, int i, int n4) {
    if (i >= n4) return;
    float4 v = ((const float4*)in)[i];
    __nv_bfloat16 h0 = __float2bfloat16(v.x);
    __nv_bfloat16 h1 = __float2bfloat16(v.y);
    __nv_bfloat16 h2 = __float2bfloat16(v.z);
    __nv_bfloat16 h3 = __float2bfloat16(v.w);
    __nv_bfloat16 l0 = __float2bfloat16(v.x - __bfloat162float(h0));
    __nv_bfloat16 l1 = __float2bfloat16(v.y - __bfloat162float(h1));
    __nv_bfloat16 l2 = __float2bfloat16(v.z - __bfloat162float(h2));
    __nv_bfloat16 l3 = __float2bfloat16(v.w - __bfloat162float(h3));
    ((__nv_bfloat162*)hi)[2 * i + 0] = __halves2bfloat162(h0, h1);
    ((__nv_bfloat162*)hi)[2 * i + 1] = __halves2bfloat162(h2, h3);
    ((__nv_bfloat162*)lo)[2 * i + 0] = __halves2bfloat162(l0, l1);
    ((__nv_bfloat162*)lo)[2 * i + 1] = __halves2bfloat162(l2, l3);
}

__global__ __launch_bounds__(256)
void split_kernel(const float* __restrict__ in, __nv_bfloat16* __restrict__ hi,
                  __nv_bfloat16* __restrict__ lo, int n4) {
    split_body(in, hi, lo, blockIdx.x * blockDim.x + threadIdx.x, n4);
}

__global__ __launch_bounds__(256)
void split3_kernel(const float* __restrict__ i0, __nv_bfloat16* __restrict__ h0, __nv_bfloat16* __restrict__ l0,
                   const float* __restrict__ i1, __nv_bfloat16* __restrict__ h1, __nv_bfloat16* __restrict__ l1,
                   const float* __restrict__ i2, __nv_bfloat16* __restrict__ h2, __nv_bfloat16* __restrict__ l2,
                   int n4) {
    const int i = blockIdx.x * blockDim.x + threadIdx.x;
    if (blockIdx.y == 0)      split_body(i0, h0, l0, i, n4);
    else if (blockIdx.y == 1) split_body(i1, h1, l1, i, n4);
    else                      split_body(i2, h2, l2, i, n4);
}

// ---------------------------------------------------------------------------
// Split-bf16 tensor-core GEMM (mma.sync).  BK=32, 3-stage ring with
// PER-STAGE mbarriers (full/empty, count=256) instead of __syncthreads —
// the mainloop has NO block-wide barrier, so warps free-run with up to
// ~2 chunks of drift and the tensor pipe is not drained at chunk edges.
//   full[st]:  cp.async.mbarrier.arrive.NOINC per thread (data landed)
//   empty[st]: mbarrier.arrive per thread after its last ldsm of the stage
// K-major smem arrays: 128 rows x 64B, XOR-swizzled (g' = g ^ ((r>>1)&3)).
// B [K][N] (trans) array: 32 rows x 272B pitch.  2 CTAs/SM.
// ---------------------------------------------------------------------------
#define ARR_KMAJ 8192                     // 128 * 64
#define BSZ_TRUE 8192
#define BSZ_FALSE 8704                    // 32 * 272
#define ST_BYTES(BT_) (2 * ARR_KMAJ + 2 * ((BT_) ? BSZ_TRUE : BSZ_FALSE))
#define GM_SMEM(BT_)  (3 * ST_BYTES(BT_))

template <bool BT, bool HAS_BIAS, bool WF32, bool WBF16, bool QKV3>
__global__ __launch_bounds__(256, 2)
void mma_gemm(const __nv_bfloat16* __restrict__ Ah, const __nv_bfloat16* __restrict__ Al,
              const __nv_bfloat16* __restrict__ Bh0, const __nv_bfloat16* __restrict__ Bl0,
              const __nv_bfloat16* __restrict__ Bh1, const __nv_bfloat16* __restrict__ Bl1,
              const __nv_bfloat16* __restrict__ Bh2, const __nv_bfloat16* __restrict__ Bl2,
              const float* __restrict__ bias0, const float* __restrict__ bias1,
              const float* __restrict__ bias2,
              float* __restrict__ Cf,
              __nv_bfloat16* __restrict__ Ch0, __nv_bfloat16* __restrict__ Cl0,
              __nv_bfloat16* __restrict__ Ch1, __nv_bfloat16* __restrict__ Cl1,
              __nv_bfloat16* __restrict__ Ch2, __nv_bfloat16* __restrict__ Cl2,
              int M, int Ncols, int Kdim, float alpha) {
    extern __shared__ __nv_bfloat16 sm[];
    __shared__ __align__(8) uint64_t s_mbar[6];   // full[0..2], empty[0..2]

    constexpr int BSZ = BT ? BSZ_TRUE : BSZ_FALSE;
    constexpr int STB = 2 * ARR_KMAJ + 2 * BSZ;
    constexpr uint32_t OFF_AL = ARR_KMAJ;
    constexpr uint32_t OFF_BH = 2 * ARR_KMAJ;
    constexpr uint32_t OFF_BL = 2 * ARR_KMAJ + BSZ;

    const int tid  = threadIdx.x;
    const int lane = tid & 31;
    const int wid  = tid >> 5;
    const int wm   = (wid >> 2) * 64;
    const int wn   = (wid & 3) * 32;
    const int bm   = blockIdx.y * 128;
    const int bn   = blockIdx.x * 128;

    const __nv_bfloat16* Bh = Bh0;
    const __nv_bfloat16* Bl = Bl0;
    const float* bias = bias0;
    __nv_bfloat16* Ch = Ch0;
    __nv_bfloat16* Cl = Cl0;
    if (QKV3) {
        if (blockIdx.z == 1) { Bh = Bh1; Bl = Bl1; bias = bias1; Ch = Ch1; Cl = Cl1; }
        else if (blockIdx.z == 2) { Bh = Bh2; Bl = Bl2; bias = bias2; Ch = Ch2; Cl = Cl2; }
    }

    float acc[4][4][4];
#pragma unroll
    for (int i = 0; i < 4; i++)
#pragma unroll
        for (int j = 0; j < 4; j++)
#pragma unroll
            for (int k = 0; k < 4; k++) acc[i][j][k] = 0.f;

    const uint32_t smb = smem_u32(&sm[0]);
    const uint32_t mb  = smem_u32(&s_mbar[0]);
    // full(st) = mb + st*8 ; empty(st) = mb + 24 + st*8

    if (tid == 0) {
#pragma unroll
        for (int s = 0; s < 3; s++) {
            mbar_init(mb + s * 8, 256);        // full
            mbar_init(mb + 24 + s * 8, 256);   // empty
        }
    }
    __syncthreads();   // only block-wide barrier: after mbarrier init

    // ldsm row bases + swizzle masks (K-major arrays)
    uint32_t rowa[4], swza[4];
#pragma unroll
    for (int mi = 0; mi < 4; mi++) {
        const int r = wm + mi * 16 + (lane & 15);
        rowa[mi] = (uint32_t)(r * 64);
        swza[mi] = (uint32_t)((r >> 1) & 3);
    }
    uint32_t rowb[2], swzb[2], offbt[2];
#pragma unroll
    for (int nb = 0; nb < 2; nb++) {
        if (BT) {
            const int r = wn + nb * 16 + (lane & 15);
            rowb[nb] = (uint32_t)(r * 64);
            swzb[nb] = (uint32_t)((r >> 1) & 3);
        } else {
            offbt[nb] = (uint32_t)((lane & 15) * 272 + (wn + nb * 16 + (lane >> 4) * 8) * 2);
        }
    }

    const int nk = Kdim >> 5;   // BK=32 chunks (always >= 3 here)

    auto produce = [&](int st, int kc) {
        const uint32_t base = smb + (uint32_t)st * STB;
        const int k0 = kc * 32;
#pragma unroll
        for (int p = 0; p < 2; p++) {
            const int G = tid * 2 + p;
            {
                const int r = G >> 2, g = G & 3;
                const uint32_t d = (uint32_t)(r * 64 + ((g ^ ((r >> 1) & 3)) * 16));
                const size_t o = (size_t)(bm + r) * Kdim + k0 + g * 8;
                cp_async16(base + d, Ah + o);
                cp_async16(base + OFF_AL + d, Al + o);
            }
            if (BT) {
                const int r = G >> 2, g = G & 3;
                const uint32_t d = (uint32_t)(r * 64 + ((g ^ ((r >> 1) & 3)) * 16));
                const size_t o = (size_t)(bn + r) * Kdim + k0 + g * 8;
                cp_async16(base + OFF_BH + d, Bh + o);
                cp_async16(base + OFF_BL + d, Bl + o);
            } else {
                const int r = G >> 4, c = G & 15;
                const uint32_t d = (uint32_t)(r * 272 + c * 16);
                const size_t o = (size_t)(k0 + r) * Ncols + bn + c * 8;
                cp_async16(base + OFF_BH + d, Bh + o);
                cp_async16(base + OFF_BL + d, Bl + o);
            }
        }
        cpasync_mbar_arrive_noinc(mb + st * 8);   // one real arrival per thread
    };

    // prologue: fill all 3 stages
    produce(0, 0);
    produce(1, 1);
    produce(2, 2);

    uint32_t fpbits = 0;   // full-wait parity per slot (bit st)
    uint32_t epbits = 0;   // empty-wait parity per slot (bit st)

    for (int i = 0; i < nk; i++) {
        const int st = i % 3;
        const uint32_t base = smb + (uint32_t)st * STB;

        mbar_wait(mb + st * 8, (fpbits >> st) & 1u);
        fpbits ^= (1u << st);

#pragma unroll
        for (int ks = 0; ks < 2; ks++) {
            const uint32_t gbase = (uint32_t)(ks * 2 + (lane >> 4));  // logical granule

            // ---- group 1: A-hi, B-hi -> hh MMAs
            uint32_t fah[4][4];
#pragma unroll
            for (int mi = 0; mi < 4; mi++) {
                const uint32_t d = rowa[mi] + ((gbase ^ swza[mi]) * 16);
                ldsm_x4(fah[mi][0], fah[mi][1], fah[mi][2], fah[mi][3], base + d);
            }
            uint32_t fbh[4][2];
#pragma unroll
            for (int nb = 0; nb < 2; nb++) {
                uint32_t r0, r1, r2, r3;
                if (BT) {
                    const uint32_t d = rowb[nb] + ((gbase ^ swzb[nb]) * 16);
                    ldsm_x4(r0, r1, r2, r3, base + OFF_BH + d);
                    fbh[2 * nb][0] = r0; fbh[2 * nb][1] = r2;
                    fbh[2 * nb + 1][0] = r1; fbh[2 * nb + 1][1] = r3;
                } else {
                    const uint32_t d = offbt[nb] + (uint32_t)(ks * 16 * 272);
                    ldsm_x4_t(r0, r1, r2, r3, base + OFF_BH + d);
                    fbh[2 * nb][0] = r0; fbh[2 * nb][1] = r1;
                    fbh[2 * nb + 1][0] = r2; fbh[2 * nb + 1][1] = r3;
                }
            }
#pragma unroll
            for (int mi = 0; mi < 4; mi++)
#pragma unroll
                for (int ni = 0; ni < 4; ni++)
                    mma16816(acc[mi][ni], fah[mi], fbh[ni]);

            // ---- group 2: B-lo -> hl MMAs
            uint32_t fbl[4][2];
#pragma unroll
            for (int nb = 0; nb < 2; nb++) {
                uint32_t r0, r1, r2, r3;
                if (BT) {
                    const uint32_t d = rowb[nb] + ((gbase ^ swzb[nb]) * 16);
                    ldsm_x4(r0, r1, r2, r3, base + OFF_BL + d);
                    fbl[2 * nb][0] = r0; fbl[2 * nb][1] = r2;
                    fbl[2 * nb + 1][0] = r1; fbl[2 * nb + 1][1] = r3;
                } else {
                    const uint32_t d = offbt[nb] + (uint32_t)(ks * 16 * 272);
                    ldsm_x4_t(r0, r1, r2, r3, base + OFF_BL + d);
                    fbl[2 * nb][0] = r0; fbl[2 * nb][1] = r1;
                    fbl[2 * nb + 1][0] = r2; fbl[2 * nb + 1][1] = r3;
                }
            }
#pragma unroll
            for (int mi = 0; mi < 4; mi++)
#pragma unroll
                for (int ni = 0; ni < 4; ni++)
                    mma16816(acc[mi][ni], fah[mi], fbl[ni]);

            // ---- group 3: A-lo -> lh MMAs
            uint32_t fal[4][4];
#pragma unroll
            for (int mi = 0; mi < 4; mi++) {
                const uint32_t d = rowa[mi] + ((gbase ^ swza[mi]) * 16);
                ldsm_x4(fal[mi][0], fal[mi][1], fal[mi][2], fal[mi][3], base + OFF_AL + d);
            }
#pragma unroll
            for (int mi = 0; mi < 4; mi++)
#pragma unroll
                for (int ni = 0; ni < 4; ni++)
                    mma16816(acc[mi][ni], fal[mi], fbh[ni]);
        }

        // all my smem reads of this stage retired (ldsm is synchronous)
        mbar_arrive(mb + 24 + st * 8);   // empty[st]

        if (i + 3 < nk) {
            // refill this slot once ALL warps are done with chunk i
            mbar_wait(mb + 24 + st * 8, (epbits >> st) & 1u);
            epbits ^= (1u << st);
            produce(st, i + 3);
        }
    }

    // ---- epilogue (direct from registers)
#pragma unroll
    for (int mi = 0; mi < 4; mi++) {
#pragma unroll
        for (int ni = 0; ni < 4; ni++) {
#pragma unroll
            for (int h = 0; h < 2; h++) {
                const int r = bm + wm + mi * 16 + (lane >> 2) + h * 8;
                const int c = bn + wn + ni * 8 + ((lane & 3) << 1);
                float v0 = acc[mi][ni][2 * h + 0] * alpha;
                float v1 = acc[mi][ni][2 * h + 1] * alpha;
                if (HAS_BIAS) { v0 += bias[c]; v1 += bias[c + 1]; }
                const size_t idx = (size_t)r * Ncols + c;
                if (WF32) {
                    float2 o; o.x = v0; o.y = v1;
                    *(float2*)(Cf + idx) = o;
                }
                if (WBF16) {
                    __nv_bfloat16 h0 = __float2bfloat16(v0);
                    __nv_bfloat16 h1 = __float2bfloat16(v1);
                    __nv_bfloat16 l0 = __float2bfloat16(v0 - __bfloat162float(h0));
                    __nv_bfloat16 l1 = __float2bfloat16(v1 - __bfloat162float(h1));
                    *(__nv_bfloat162*)(Ch + idx) = __halves2bfloat162(h0, h1);
                    *(__nv_bfloat162*)(Cl + idx) = __halves2bfloat162(l0, l1);
                }
            }
        }
    }
}

// ---------------------------------------------------------------------------
// Row softmax over fp32 S; emits bf16 hi/lo of the probabilities.
// ---------------------------------------------------------------------------
__global__ __launch_bounds__(256)
void softmax_split(const float* __restrict__ S, __nv_bfloat16* __restrict__ Sh,
                   __nv_bfloat16* __restrict__ Sl) {
    constexpr int T = 256;
    constexpr int VPT = N_TOK / T;  // 16
    const int row = blockIdx.x;
    const int tid = threadIdx.x;
    const float* p = S + (size_t)row * N_TOK;

    float v[VPT];
    float m = -3.0e38f;
#pragma unroll
    for (int i = 0; i < VPT; i++) {
        v[i] = p[tid + i * T];
        m = fmaxf(m, v[i]);
    }
    __shared__ float red[T];
    red[tid] = m;
    __syncthreads();
    for (int s = T / 2; s > 0; s >>= 1) {
        if (tid < s) red[tid] = fmaxf(red[tid], red[tid + s]);
        __syncthreads();
    }
    m = red[0];
    __syncthreads();

    float sum = 0.f;
#pragma unroll
    for (int i = 0; i < VPT; i++) {
        v[i] = __expf(v[i] - m);
        sum += v[i];
    }
    red[tid] = sum;
    __syncthreads();
    for (int s = T / 2; s > 0; s >>= 1) {
        if (tid < s) red[tid] += red[tid + s];
        __syncthreads();
    }
    const float inv = 1.f / red[0];
#pragma unroll
    for (int i = 0; i < VPT; i++) {
        const float w = v[i] * inv;
        const __nv_bfloat16 h = __float2bfloat16(w);
        const __nv_bfloat16 l = __float2bfloat16(w - __bfloat162float(h));
        Sh[(size_t)row * N_TOK + tid + i * T] = h;
        Sl[(size_t)row * N_TOK + tid + i * T] = l;
    }
}

// ---------------------------------------------------------------------------
// Launch
// ---------------------------------------------------------------------------
extern "C" void kernel_launch(void* const* d_in, const int* in_sizes, int n_in,
                              void* d_out, int out_size) {
    const float* x  = (const float*)d_in[0];
    const float* W1 = (const float*)d_in[1];
    const float* b1 = (const float*)d_in[2];
    const float* W2 = (const float*)d_in[3];
    const float* b2 = (const float*)d_in[4];
    const float* W3 = (const float*)d_in[5];
    const float* b3 = (const float*)d_in[6];
    float* out = (float*)d_out;

    __nv_bfloat16 *xh, *xl, *w1h, *w1l, *w2h, *w2l, *w3h, *w3l;
    __nv_bfloat16 *qh, *ql, *kh, *kl, *vh, *vl, *sh, *sl;
    float* S;
    cudaGetSymbolAddress((void**)&xh, g_xh);   cudaGetSymbolAddress((void**)&xl, g_xl);
    cudaGetSymbolAddress((void**)&w1h, g_w1h); cudaGetSymbolAddress((void**)&w1l, g_w1l);
    cudaGetSymbolAddress((void**)&w2h, g_w2h); cudaGetSymbolAddress((void**)&w2l, g_w2l);
    cudaGetSymbolAddress((void**)&w3h, g_w3h); cudaGetSymbolAddress((void**)&w3l, g_w3l);
    cudaGetSymbolAddress((void**)&qh, g_qh);   cudaGetSymbolAddress((void**)&ql, g_ql);
    cudaGetSymbolAddress((void**)&kh, g_kh);   cudaGetSymbolAddress((void**)&kl, g_kl);
    cudaGetSymbolAddress((void**)&vh, g_vh);   cudaGetSymbolAddress((void**)&vl, g_vl);
    cudaGetSymbolAddress((void**)&sh, g_sh);   cudaGetSymbolAddress((void**)&sl, g_sl);
    cudaGetSymbolAddress((void**)&S, g_S);

    cudaFuncSetAttribute(mma_gemm<true, true, false, true, true>,
                         cudaFuncAttributeMaxDynamicSharedMemorySize, GM_SMEM(true));
    cudaFuncSetAttribute(mma_gemm<true, false, true, false, false>,
                         cudaFuncAttributeMaxDynamicSharedMemorySize, GM_SMEM(true));
    cudaFuncSetAttribute(mma_gemm<false, false, true, false, false>,
                         cudaFuncAttributeMaxDynamicSharedMemorySize, GM_SMEM(false));

    const dim3 blk(256);

    const int nx4 = N_TOK * D_MODEL / 4;
    const int nw4 = D_MODEL * D_MODEL / 4;
    split_kernel<<<(nx4 + 255) / 256, blk>>>(x, xh, xl, nx4);
    split3_kernel<<<dim3((nw4 + 255) / 256, 3), blk>>>(
        W1, w1h, w1l, W2, w2h, w2l, W3, w3h, w3l, nw4);

    const dim3 grid_qkv(D_MODEL / 128, N_TOK / 128, 3);  // (8, 32, 3)
    const dim3 grid_attn(N_TOK / 128, N_TOK / 128);      // (32, 32)
    const dim3 grid_pv(D_MODEL / 128, N_TOK / 128);      // (8, 32)

    // merged Q/K/V projections (bf16 hi/lo out, +bias)
    mma_gemm<true, true, false, true, true><<<grid_qkv, blk, GM_SMEM(true)>>>(
        xh, xl, w1h, w1l, w2h, w2l, w3h, w3l, b1, b2, b3,
        nullptr, qh, ql, kh, kl, vh, vl, N_TOK, D_MODEL, D_MODEL, 1.f);

    // S = scale * K @ Q^T  (fp32 out)
    const float scale = rsqrtf((float)D_MODEL);
    mma_gemm<true, false, true, false, false><<<grid_attn, blk, GM_SMEM(true)>>>(
        kh, kl, qh, ql, nullptr, nullptr, nullptr, nullptr, nullptr, nullptr, nullptr,
        S, nullptr, nullptr, nullptr, nullptr, nullptr, nullptr,
        N_TOK, N_TOK, D_MODEL, scale);

    // softmax rows -> bf16 hi/lo probabilities
    softmax_split<<<N_TOK, blk>>>(S, sh, sl);

    // out = P @ V (fp32 out)
    mma_gemm<false, false, true, false, false><<<grid_pv, blk, GM_SMEM(false)>>>(
        sh, sl, vh, vl, nullptr, nullptr, nullptr, nullptr, nullptr, nullptr, nullptr,
        out, nullptr, nullptr, nullptr, nullptr, nullptr, nullptr,
        N_TOK, D_MODEL, N_TOK, 1.f);
}

// round 16
// speedup vs baseline: 1.4776x; 1.4386x over previous
#include <cuda_runtime.h>
#include <cuda_fp16.h>
#include <cstdint>

#define N_TOK 4096
#define D_MODEL 1024

// ---------------------------------------------------------------------------
// Scratch (__device__ globals; no allocations allowed)
// fp16 split: hi = fp16(a), lo = fp16(a - hi).  2-term GEMM: Ah*Bh + Ah*Bl
// (A operands need hi only; B operands need hi+lo).
// ---------------------------------------------------------------------------
__device__ __half g_xh [(size_t)N_TOK * D_MODEL];                 // A of QKV
__device__ __half g_w1h[(size_t)D_MODEL * D_MODEL];
__device__ __half g_w1l[(size_t)D_MODEL * D_MODEL];
__device__ __half g_w2h[(size_t)D_MODEL * D_MODEL];
__device__ __half g_w2l[(size_t)D_MODEL * D_MODEL];
__device__ __half g_w3h[(size_t)D_MODEL * D_MODEL];
__device__ __half g_w3l[(size_t)D_MODEL * D_MODEL];
__device__ __half g_qh [(size_t)N_TOK * D_MODEL];                 // B of attn
__device__ __half g_ql [(size_t)N_TOK * D_MODEL];
__device__ __half g_kh [(size_t)N_TOK * D_MODEL];                 // A of attn
__device__ __half g_kl [(size_t)N_TOK * D_MODEL];                 // (unused; epilogue symmetry)
__device__ __half g_vh [(size_t)N_TOK * D_MODEL];                 // B of PV
__device__ __half g_vl [(size_t)N_TOK * D_MODEL];
__device__ float  g_S  [(size_t)N_TOK * N_TOK];
__device__ __half g_sh [(size_t)N_TOK * N_TOK];                   // A of PV (hi only)

// ---------------------------------------------------------------------------
// PTX helpers
// ---------------------------------------------------------------------------
__device__ __forceinline__ uint32_t smem_u32(const void* p) {
    return (uint32_t)__cvta_generic_to_shared(p);
}
__device__ __forceinline__ void cp_async16(uint32_t dst, const void* src) {
    asm volatile("cp.async.cg.shared.global [%0], [%1], 16;\n" :: "r"(dst), "l"(src));
}
__device__ __forceinline__ void cp_commit() {
    asm volatile("cp.async.commit_group;\n" ::: "memory");
}
template <int N>
__device__ __forceinline__ void cp_wait() {
    asm volatile("cp.async.wait_group %0;\n" :: "n"(N) : "memory");
}
__device__ __forceinline__ void ldsm_x4(uint32_t& r0, uint32_t& r1, uint32_t& r2, uint32_t& r3,
                                        uint32_t addr) {
    asm volatile("ldmatrix.sync.aligned.m8n8.x4.shared.b16 {%0,%1,%2,%3}, [%4];\n"
                 : "=r"(r0), "=r"(r1), "=r"(r2), "=r"(r3) : "r"(addr));
}
__device__ __forceinline__ void ldsm_x4_t(uint32_t& r0, uint32_t& r1, uint32_t& r2, uint32_t& r3,
                                          uint32_t addr) {
    asm volatile("ldmatrix.sync.aligned.m8n8.x4.trans.shared.b16 {%0,%1,%2,%3}, [%4];\n"
                 : "=r"(r0), "=r"(r1), "=r"(r2), "=r"(r3) : "r"(addr));
}
__device__ __forceinline__ void mma16816(float* c, const uint32_t* a, const uint32_t* b) {
    asm volatile(
        "mma.sync.aligned.m16n8k16.row.col.f32.f16.f16.f32 "
        "{%0,%1,%2,%3}, {%4,%5,%6,%7}, {%8,%9}, {%0,%1,%2,%3};\n"
        : "+f"(c[0]), "+f"(c[1]), "+f"(c[2]), "+f"(c[3])
        : "r"(a[0]), "r"(a[1]), "r"(a[2]), "r"(a[3]), "r"(b[0]), "r"(b[1]));
}

// ---------------------------------------------------------------------------
// Split fp32 -> (hi, lo) fp16
// ---------------------------------------------------------------------------
__device__ __forceinline__ void split_body(const float* __restrict__ in,
                                           __half* __restrict__ hi,
                                           __half* __restrict__ lo, int i, int n4) {
    if (i >= n4) return;
    float4 v = ((const float4*)in)[i];
    __half h0 = __float2half(v.x);
    __half h1 = __float2half(v.y);
    __half h2 = __float2half(v.z);
    __half h3 = __float2half(v.w);
    __half l0 = __float2half(v.x - __half2float(h0));
    __half l1 = __float2half(v.y - __half2float(h1));
    __half l2 = __float2half(v.z - __half2float(h2));
    __half l3 = __float2half(v.w - __half2float(h3));
    ((__half2*)hi)[2 * i + 0] = __halves2half2(h0, h1);
    ((__half2*)hi)[2 * i + 1] = __halves2half2(h2, h3);
    ((__half2*)lo)[2 * i + 0] = __halves2half2(l0, l1);
    ((__half2*)lo)[2 * i + 1] = __halves2half2(l2, l3);
}

// hi-only split (for A operands)
__global__ __launch_bounds__(256)
void split_h_kernel(const float* __restrict__ in, __half* __restrict__ hi, int n4) {
    int i = blockIdx.x * blockDim.x + threadIdx.x;
    if (i >= n4) return;
    float4 v = ((const float4*)in)[i];
    ((__half2*)hi)[2 * i + 0] = __halves2half2(__float2half(v.x), __float2half(v.y));
    ((__half2*)hi)[2 * i + 1] = __halves2half2(__float2half(v.z), __float2half(v.w));
}

__global__ __launch_bounds__(256)
void split3_kernel(const float* __restrict__ i0, __half* __restrict__ h0, __half* __restrict__ l0,
                   const float* __restrict__ i1, __half* __restrict__ h1, __half* __restrict__ l1,
                   const float* __restrict__ i2, __half* __restrict__ h2, __half* __restrict__ l2,
                   int n4) {
    const int i = blockIdx.x * blockDim.x + threadIdx.x;
    if (blockIdx.y == 0)      split_body(i0, h0, l0, i, n4);
    else if (blockIdx.y == 1) split_body(i1, h1, l1, i, n4);
    else                      split_body(i2, h2, l2, i, n4);
}

// ---------------------------------------------------------------------------
// 2-term fp16 split tensor-core GEMM (mma.sync):
//   C = alpha * ( Ah @ op(Bh) + Ah @ op(Bl) ) (+ bias)
// BK=32, 3-stage cp.async pipeline, one __syncthreads per chunk, 2 CTAs/SM.
//   BT=true : B hi/lo is [Ncols,Kdim] row-major (A @ B^T)
//   BT=false: B hi/lo is [Kdim,Ncols] row-major (A @ B)
// Block 128x128, 8 warps (warp tile 64x32).
// K-major smem arrays: 128 rows x 64B, XOR-swizzled (g' = g ^ ((r>>1)&3)).
// B [K][N] (trans) array: 32 rows x 272B pitch.
// Stage = Ah + Bh + Bl (3 arrays; no Al).
// ---------------------------------------------------------------------------
#define ARR_KMAJ 8192                     // 128 * 64
#define BSZ_TRUE 8192
#define BSZ_FALSE 8704                    // 32 * 272
#define ST_BYTES(BT_) (ARR_KMAJ + 2 * ((BT_) ? BSZ_TRUE : BSZ_FALSE))
#define GM_SMEM(BT_)  (3 * ST_BYTES(BT_))

template <bool BT, bool HAS_BIAS, bool WF32, bool WF16, bool QKV3>
__global__ __launch_bounds__(256, 2)
void mma_gemm(const __half* __restrict__ Ah,
              const __half* __restrict__ Bh0, const __half* __restrict__ Bl0,
              const __half* __restrict__ Bh1, const __half* __restrict__ Bl1,
              const __half* __restrict__ Bh2, const __half* __restrict__ Bl2,
              const float* __restrict__ bias0, const float* __restrict__ bias1,
              const float* __restrict__ bias2,
              float* __restrict__ Cf,
              __half* __restrict__ Ch0, __half* __restrict__ Cl0,
              __half* __restrict__ Ch1, __half* __restrict__ Cl1,
              __half* __restrict__ Ch2, __half* __restrict__ Cl2,
              int M, int Ncols, int Kdim, float alpha) {
    extern __shared__ __half sm[];

    constexpr int BSZ = BT ? BSZ_TRUE : BSZ_FALSE;
    constexpr int STB = ARR_KMAJ + 2 * BSZ;
    constexpr uint32_t OFF_BH = ARR_KMAJ;
    constexpr uint32_t OFF_BL = ARR_KMAJ + BSZ;

    const int tid  = threadIdx.x;
    const int lane = tid & 31;
    const int wid  = tid >> 5;
    const int wm   = (wid >> 2) * 64;
    const int wn   = (wid & 3) * 32;
    const int bm   = blockIdx.y * 128;
    const int bn   = blockIdx.x * 128;

    const __half* Bh = Bh0;
    const __half* Bl = Bl0;
    const float* bias = bias0;
    __half* Ch = Ch0;
    __half* Cl = Cl0;
    if (QKV3) {
        if (blockIdx.z == 1) { Bh = Bh1; Bl = Bl1; bias = bias1; Ch = Ch1; Cl = Cl1; }
        else if (blockIdx.z == 2) { Bh = Bh2; Bl = Bl2; bias = bias2; Ch = Ch2; Cl = Cl2; }
    }

    float acc[4][4][4];
#pragma unroll
    for (int i = 0; i < 4; i++)
#pragma unroll
        for (int j = 0; j < 4; j++)
#pragma unroll
            for (int k = 0; k < 4; k++) acc[i][j][k] = 0.f;

    const uint32_t smb = smem_u32(&sm[0]);

    // ldsm row bases + swizzle masks (K-major arrays)
    uint32_t rowa[4], swza[4];
#pragma unroll
    for (int mi = 0; mi < 4; mi++) {
        const int r = wm + mi * 16 + (lane & 15);
        rowa[mi] = (uint32_t)(r * 64);
        swza[mi] = (uint32_t)((r >> 1) & 3);
    }
    uint32_t rowb[2], swzb[2], offbt[2];
#pragma unroll
    for (int nb = 0; nb < 2; nb++) {
        if (BT) {
            const int r = wn + nb * 16 + (lane & 15);
            rowb[nb] = (uint32_t)(r * 64);
            swzb[nb] = (uint32_t)((r >> 1) & 3);
        } else {
            offbt[nb] = (uint32_t)((lane & 15) * 272 + (wn + nb * 16 + (lane >> 4) * 8) * 2);
        }
    }

    const int nk = Kdim >> 5;   // BK=32 chunks

    auto load_stage = [&](int st, int kc) {
        const uint32_t base = smb + (uint32_t)st * STB;
        const int k0 = kc * 32;
#pragma unroll
        for (int p = 0; p < 2; p++) {
            const int G = tid * 2 + p;
            {   // A hi (K-major, 64B rows, swizzled granules)
                const int r = G >> 2, g = G & 3;
                const uint32_t d = (uint32_t)(r * 64 + ((g ^ ((r >> 1) & 3)) * 16));
                const size_t o = (size_t)(bm + r) * Kdim + k0 + g * 8;
                cp_async16(base + d, Ah + o);
            }
            if (BT) {
                const int r = G >> 2, g = G & 3;
                const uint32_t d = (uint32_t)(r * 64 + ((g ^ ((r >> 1) & 3)) * 16));
                const size_t o = (size_t)(bn + r) * Kdim + k0 + g * 8;
                cp_async16(base + OFF_BH + d, Bh + o);
                cp_async16(base + OFF_BL + d, Bl + o);
            } else {
                const int r = G >> 4, c = G & 15;
                const uint32_t d = (uint32_t)(r * 272 + c * 16);
                const size_t o = (size_t)(k0 + r) * Ncols + bn + c * 8;
                cp_async16(base + OFF_BH + d, Bh + o);
                cp_async16(base + OFF_BL + d, Bl + o);
            }
        }
        cp_commit();
    };

    load_stage(0, 0);
    if (nk > 1) load_stage(1, 1);

    for (int i = 0; i < nk; i++) {
        const int st = i % 3;
        if (i + 1 < nk) cp_wait<1>();
        else            cp_wait<0>();
        __syncthreads();
        if (i + 2 < nk) load_stage((i + 2) % 3, i + 2);

        const uint32_t base = smb + (uint32_t)st * STB;

#pragma unroll
        for (int ks = 0; ks < 2; ks++) {
            const uint32_t gbase = (uint32_t)(ks * 2 + (lane >> 4));  // logical granule

            // A-hi fragments
            uint32_t fah[4][4];
#pragma unroll
            for (int mi = 0; mi < 4; mi++) {
                const uint32_t d = rowa[mi] + ((gbase ^ swza[mi]) * 16);
                ldsm_x4(fah[mi][0], fah[mi][1], fah[mi][2], fah[mi][3], base + d);
            }
            // B-hi fragments -> hh MMAs
            uint32_t fbh[4][2];
#pragma unroll
            for (int nb = 0; nb < 2; nb++) {
                uint32_t r0, r1, r2, r3;
                if (BT) {
                    const uint32_t d = rowb[nb] + ((gbase ^ swzb[nb]) * 16);
                    ldsm_x4(r0, r1, r2, r3, base + OFF_BH + d);
                    fbh[2 * nb][0] = r0; fbh[2 * nb][1] = r2;
                    fbh[2 * nb + 1][0] = r1; fbh[2 * nb + 1][1] = r3;
                } else {
                    const uint32_t d = offbt[nb] + (uint32_t)(ks * 16 * 272);
                    ldsm_x4_t(r0, r1, r2, r3, base + OFF_BH + d);
                    fbh[2 * nb][0] = r0; fbh[2 * nb][1] = r1;
                    fbh[2 * nb + 1][0] = r2; fbh[2 * nb + 1][1] = r3;
                }
            }
#pragma unroll
            for (int mi = 0; mi < 4; mi++)
#pragma unroll
                for (int ni = 0; ni < 4; ni++)
                    mma16816(acc[mi][ni], fah[mi], fbh[ni]);

            // B-lo fragments -> hl MMAs
            uint32_t fbl[4][2];
#pragma unroll
            for (int nb = 0; nb < 2; nb++) {
                uint32_t r0, r1, r2, r3;
                if (BT) {
                    const uint32_t d = rowb[nb] + ((gbase ^ swzb[nb]) * 16);
                    ldsm_x4(r0, r1, r2, r3, base + OFF_BL + d);
                    fbl[2 * nb][0] = r0; fbl[2 * nb][1] = r2;
                    fbl[2 * nb + 1][0] = r1; fbl[2 * nb + 1][1] = r3;
                } else {
                    const uint32_t d = offbt[nb] + (uint32_t)(ks * 16 * 272);
                    ldsm_x4_t(r0, r1, r2, r3, base + OFF_BL + d);
                    fbl[2 * nb][0] = r0; fbl[2 * nb][1] = r1;
                    fbl[2 * nb + 1][0] = r2; fbl[2 * nb + 1][1] = r3;
                }
            }
#pragma unroll
            for (int mi = 0; mi < 4; mi++)
#pragma unroll
                for (int ni = 0; ni < 4; ni++)
                    mma16816(acc[mi][ni], fah[mi], fbl[ni]);
        }
    }

    // ---- epilogue
#pragma unroll
    for (int mi = 0; mi < 4; mi++) {
#pragma unroll
        for (int ni = 0; ni < 4; ni++) {
#pragma unroll
            for (int h = 0; h < 2; h++) {
                const int r = bm + wm + mi * 16 + (lane >> 2) + h * 8;
                const int c = bn + wn + ni * 8 + ((lane & 3) << 1);
                float v0 = acc[mi][ni][2 * h + 0] * alpha;
                float v1 = acc[mi][ni][2 * h + 1] * alpha;
                if (HAS_BIAS) { v0 += bias[c]; v1 += bias[c + 1]; }
                const size_t idx = (size_t)r * Ncols + c;
                if (WF32) {
                    float2 o; o.x = v0; o.y = v1;
                    *(float2*)(Cf + idx) = o;
                }
                if (WF16) {
                    __half h0 = __float2half(v0);
                    __half h1 = __float2half(v1);
                    __half l0 = __float2half(v0 - __half2float(h0));
                    __half l1 = __float2half(v1 - __half2float(h1));
                    *(__half2*)(Ch + idx) = __halves2half2(h0, h1);
                    *(__half2*)(Cl + idx) = __halves2half2(l0, l1);
                }
            }
        }
    }
}

// ---------------------------------------------------------------------------
// Row softmax over fp32 S; emits fp16 hi of the probabilities (A operand of PV).
// ---------------------------------------------------------------------------
__global__ __launch_bounds__(256)
void softmax_h(const float* __restrict__ S, __half* __restrict__ Sh) {
    constexpr int T = 256;
    constexpr int VPT = N_TOK / T;  // 16
    const int row = blockIdx.x;
    const int tid = threadIdx.x;
    const float* p = S + (size_t)row * N_TOK;

    float v[VPT];
    float m = -3.0e38f;
#pragma unroll
    for (int i = 0; i < VPT; i++) {
        v[i] = p[tid + i * T];
        m = fmaxf(m, v[i]);
    }
    __shared__ float red[T];
    red[tid] = m;
    __syncthreads();
    for (int s = T / 2; s > 0; s >>= 1) {
        if (tid < s) red[tid] = fmaxf(red[tid], red[tid + s]);
        __syncthreads();
    }
    m = red[0];
    __syncthreads();

    float sum = 0.f;
#pragma unroll
    for (int i = 0; i < VPT; i++) {
        v[i] = __expf(v[i] - m);
        sum += v[i];
    }
    red[tid] = sum;
    __syncthreads();
    for (int s = T / 2; s > 0; s >>= 1) {
        if (tid < s) red[tid] += red[tid + s];
        __syncthreads();
    }
    const float inv = 1.f / red[0];
#pragma unroll
    for (int i = 0; i < VPT; i++)
        Sh[(size_t)row * N_TOK + tid + i * T] = __float2half(v[i] * inv);
}

// ---------------------------------------------------------------------------
// Launch
// ---------------------------------------------------------------------------
extern "C" void kernel_launch(void* const* d_in, const int* in_sizes, int n_in,
                              void* d_out, int out_size) {
    const float* x  = (const float*)d_in[0];
    const float* W1 = (const float*)d_in[1];
    const float* b1 = (const float*)d_in[2];
    const float* W2 = (const float*)d_in[3];
    const float* b2 = (const float*)d_in[4];
    const float* W3 = (const float*)d_in[5];
    const float* b3 = (const float*)d_in[6];
    float* out = (float*)d_out;

    __half *xh, *w1h, *w1l, *w2h, *w2l, *w3h, *w3l;
    __half *qh, *ql, *kh, *kl, *vh, *vl, *sh;
    float* S;
    cudaGetSymbolAddress((void**)&xh, g_xh);
    cudaGetSymbolAddress((void**)&w1h, g_w1h); cudaGetSymbolAddress((void**)&w1l, g_w1l);
    cudaGetSymbolAddress((void**)&w2h, g_w2h); cudaGetSymbolAddress((void**)&w2l, g_w2l);
    cudaGetSymbolAddress((void**)&w3h, g_w3h); cudaGetSymbolAddress((void**)&w3l, g_w3l);
    cudaGetSymbolAddress((void**)&qh, g_qh);   cudaGetSymbolAddress((void**)&ql, g_ql);
    cudaGetSymbolAddress((void**)&kh, g_kh);   cudaGetSymbolAddress((void**)&kl, g_kl);
    cudaGetSymbolAddress((void**)&vh, g_vh);   cudaGetSymbolAddress((void**)&vl, g_vl);
    cudaGetSymbolAddress((void**)&sh, g_sh);
    cudaGetSymbolAddress((void**)&S, g_S);

    cudaFuncSetAttribute(mma_gemm<true, true, false, true, true>,
                         cudaFuncAttributeMaxDynamicSharedMemorySize, GM_SMEM(true));
    cudaFuncSetAttribute(mma_gemm<true, false, true, false, false>,
                         cudaFuncAttributeMaxDynamicSharedMemorySize, GM_SMEM(true));
    cudaFuncSetAttribute(mma_gemm<false, false, true, false, false>,
                         cudaFuncAttributeMaxDynamicSharedMemorySize, GM_SMEM(false));

    const dim3 blk(256);

    const int nx4 = N_TOK * D_MODEL / 4;
    const int nw4 = D_MODEL * D_MODEL / 4;
    split_h_kernel<<<(nx4 + 255) / 256, blk>>>(x, xh, nx4);
    split3_kernel<<<dim3((nw4 + 255) / 256, 3), blk>>>(
        W1, w1h, w1l, W2, w2h, w2l, W3, w3h, w3l, nw4);

    const dim3 grid_qkv(D_MODEL / 128, N_TOK / 128, 3);  // (8, 32, 3)
    const dim3 grid_attn(N_TOK / 128, N_TOK / 128);      // (32, 32)
    const dim3 grid_pv(D_MODEL / 128, N_TOK / 128);      // (8, 32)

    // merged Q/K/V projections (fp16 hi/lo out, +bias)
    mma_gemm<true, true, false, true, true><<<grid_qkv, blk, GM_SMEM(true)>>>(
        xh, w1h, w1l, w2h, w2l, w3h, w3l, b1, b2, b3,
        nullptr, qh, ql, kh, kl, vh, vl, N_TOK, D_MODEL, D_MODEL, 1.f);

    // S = scale * K @ Q^T  (fp32 out);  A = K hi, B = Q hi/lo
    const float scale = rsqrtf((float)D_MODEL);
    mma_gemm<true, false, true, false, false><<<grid_attn, blk, GM_SMEM(true)>>>(
        kh, qh, ql, nullptr, nullptr, nullptr, nullptr, nullptr, nullptr, nullptr,
        S, nullptr, nullptr, nullptr, nullptr, nullptr, nullptr,
        N_TOK, N_TOK, D_MODEL, scale);

    // softmax rows -> fp16 hi probabilities
    softmax_h<<<N_TOK, blk>>>(S, sh);

    // out = P @ V (fp32 out);  A = P hi, B = V hi/lo
    mma_gemm<false, false, true, false, false><<<grid_pv, blk, GM_SMEM(false)>>>(
        sh, vh, vl, nullptr, nullptr, nullptr, nullptr, nullptr, nullptr, nullptr,
        out, nullptr, nullptr, nullptr, nullptr, nullptr, nullptr,
        N_TOK, D_MODEL, N_TOK, 1.f);
}

// round 17
// speedup vs baseline: 2.3582x; 1.5959x over previous
#include <cuda_runtime.h>
#include <cuda_fp16.h>
#include <cstdint>

#define N_TOK 4096
#define D_MODEL 1024

// ---------------------------------------------------------------------------
// Scratch (__device__ globals; no allocations allowed)
// Pure fp16 path: every GEMM operand is fp16(hi) only.
// ---------------------------------------------------------------------------
__device__ __half g_xh [(size_t)N_TOK * D_MODEL];
__device__ __half g_w1h[(size_t)D_MODEL * D_MODEL];
__device__ __half g_w2h[(size_t)D_MODEL * D_MODEL];
__device__ __half g_w3h[(size_t)D_MODEL * D_MODEL];
__device__ __half g_qh [(size_t)N_TOK * D_MODEL];
__device__ __half g_kh [(size_t)N_TOK * D_MODEL];
__device__ __half g_vh [(size_t)N_TOK * D_MODEL];
__device__ float  g_S  [(size_t)N_TOK * N_TOK];
__device__ __half g_sh [(size_t)N_TOK * N_TOK];

// ---------------------------------------------------------------------------
// PTX helpers
// ---------------------------------------------------------------------------
__device__ __forceinline__ uint32_t smem_u32(const void* p) {
    return (uint32_t)__cvta_generic_to_shared(p);
}
__device__ __forceinline__ void cp_async16(uint32_t dst, const void* src) {
    asm volatile("cp.async.cg.shared.global [%0], [%1], 16;\n" :: "r"(dst), "l"(src));
}
__device__ __forceinline__ void cp_commit() {
    asm volatile("cp.async.commit_group;\n" ::: "memory");
}
template <int N>
__device__ __forceinline__ void cp_wait() {
    asm volatile("cp.async.wait_group %0;\n" :: "n"(N) : "memory");
}
__device__ __forceinline__ void ldsm_x4(uint32_t& r0, uint32_t& r1, uint32_t& r2, uint32_t& r3,
                                        uint32_t addr) {
    asm volatile("ldmatrix.sync.aligned.m8n8.x4.shared.b16 {%0,%1,%2,%3}, [%4];\n"
                 : "=r"(r0), "=r"(r1), "=r"(r2), "=r"(r3) : "r"(addr));
}
__device__ __forceinline__ void ldsm_x4_t(uint32_t& r0, uint32_t& r1, uint32_t& r2, uint32_t& r3,
                                          uint32_t addr) {
    asm volatile("ldmatrix.sync.aligned.m8n8.x4.trans.shared.b16 {%0,%1,%2,%3}, [%4];\n"
                 : "=r"(r0), "=r"(r1), "=r"(r2), "=r"(r3) : "r"(addr));
}
__device__ __forceinline__ void mma16816(float* c, const uint32_t* a, const uint32_t* b) {
    asm volatile(
        "mma.sync.aligned.m16n8k16.row.col.f32.f16.f16.f32 "
        "{%0,%1,%2,%3}, {%4,%5,%6,%7}, {%8,%9}, {%0,%1,%2,%3};\n"
        : "+f"(c[0]), "+f"(c[1]), "+f"(c[2]), "+f"(c[3])
        : "r"(a[0]), "r"(a[1]), "r"(a[2]), "r"(a[3]), "r"(b[0]), "r"(b[1]));
}

// ---------------------------------------------------------------------------
// fp32 -> fp16 convert kernels
// ---------------------------------------------------------------------------
__device__ __forceinline__ void cvt_body(const float* __restrict__ in,
                                         __half* __restrict__ hi, int i, int n4) {
    if (i >= n4) return;
    float4 v = ((const float4*)in)[i];
    ((__half2*)hi)[2 * i + 0] = __halves2half2(__float2half(v.x), __float2half(v.y));
    ((__half2*)hi)[2 * i + 1] = __halves2half2(__float2half(v.z), __float2half(v.w));
}

__global__ __launch_bounds__(256)
void cvt_kernel(const float* __restrict__ in, __half* __restrict__ hi, int n4) {
    cvt_body(in, hi, blockIdx.x * blockDim.x + threadIdx.x, n4);
}

__global__ __launch_bounds__(256)
void cvt3_kernel(const float* __restrict__ i0, __half* __restrict__ h0,
                 const float* __restrict__ i1, __half* __restrict__ h1,
                 const float* __restrict__ i2, __half* __restrict__ h2, int n4) {
    const int i = blockIdx.x * blockDim.x + threadIdx.x;
    if (blockIdx.y == 0)      cvt_body(i0, h0, i, n4);
    else if (blockIdx.y == 1) cvt_body(i1, h1, i, n4);
    else                      cvt_body(i2, h2, i, n4);
}

// ---------------------------------------------------------------------------
// Plain fp16 tensor-core GEMM (mma.sync), fp32 accumulate:
//   C = alpha * A @ op(B) (+ bias)
// BK=64, 3-stage cp.async pipeline, one __syncthreads per chunk, 2 CTAs/SM.
//   BT=true : B is [Ncols,Kdim] row-major (A @ B^T)
//   BT=false: B is [Kdim,Ncols] row-major (A @ B)
// Block 128x128, 8 warps (warp tile 64x32).
// K-major smem arrays: 128 rows x 128B, standard SW128 swizzle:
//   phys granule g' = g ^ (r & 7)  (8 granules of 16B per row).
// B [K][N] (trans) array: 64 rows x 272B pitch.
// Stage = A + B.
// ---------------------------------------------------------------------------
#define ARR_KMAJ 16384                    // 128 * 128
#define BSZ_TRUE 16384
#define BSZ_FALSE 17408                   // 64 * 272
#define ST_BYTES(BT_) (ARR_KMAJ + ((BT_) ? BSZ_TRUE : BSZ_FALSE))
#define GM_SMEM(BT_)  (3 * ST_BYTES(BT_))

template <bool BT, bool HAS_BIAS, bool WF32, bool WF16, bool QKV3>
__global__ __launch_bounds__(256, 2)
void mma_gemm(const __half* __restrict__ Ah,
              const __half* __restrict__ Bh0, const __half* __restrict__ Bh1,
              const __half* __restrict__ Bh2,
              const float* __restrict__ bias0, const float* __restrict__ bias1,
              const float* __restrict__ bias2,
              float* __restrict__ Cf,
              __half* __restrict__ Ch0, __half* __restrict__ Ch1,
              __half* __restrict__ Ch2,
              int M, int Ncols, int Kdim, float alpha) {
    extern __shared__ __half sm[];

    constexpr int BSZ = BT ? BSZ_TRUE : BSZ_FALSE;
    constexpr int STB = ARR_KMAJ + BSZ;
    constexpr uint32_t OFF_B = ARR_KMAJ;

    const int tid  = threadIdx.x;
    const int lane = tid & 31;
    const int wid  = tid >> 5;
    const int wm   = (wid >> 2) * 64;
    const int wn   = (wid & 3) * 32;
    const int bm   = blockIdx.y * 128;
    const int bn   = blockIdx.x * 128;

    const __half* Bh = Bh0;
    const float* bias = bias0;
    __half* Ch = Ch0;
    if (QKV3) {
        if (blockIdx.z == 1) { Bh = Bh1; bias = bias1; Ch = Ch1; }
        else if (blockIdx.z == 2) { Bh = Bh2; bias = bias2; Ch = Ch2; }
    }

    float acc[4][4][4];
#pragma unroll
    for (int i = 0; i < 4; i++)
#pragma unroll
        for (int j = 0; j < 4; j++)
#pragma unroll
            for (int k = 0; k < 4; k++) acc[i][j][k] = 0.f;

    const uint32_t smb = smem_u32(&sm[0]);

    // ldsm row bases + swizzle masks
    uint32_t rowa[4], swza[4];
#pragma unroll
    for (int mi = 0; mi < 4; mi++) {
        const int r = wm + mi * 16 + (lane & 15);
        rowa[mi] = (uint32_t)(r * 128);
        swza[mi] = (uint32_t)(r & 7);
    }
    uint32_t rowb[2], swzb[2], offbt[2];
#pragma unroll
    for (int nb = 0; nb < 2; nb++) {
        if (BT) {
            const int r = wn + nb * 16 + (lane & 15);
            rowb[nb] = (uint32_t)(r * 128);
            swzb[nb] = (uint32_t)(r & 7);
        } else {
            offbt[nb] = (uint32_t)((lane & 15) * 272 + (wn + nb * 16 + (lane >> 4) * 8) * 2);
        }
    }

    const int nk = Kdim >> 6;   // BK=64 chunks

    auto load_stage = [&](int st, int kc) {
        const uint32_t base = smb + (uint32_t)st * STB;
        const int k0 = kc * 64;
#pragma unroll
        for (int p = 0; p < 4; p++) {
            const int G = tid * 4 + p;   // granule 0..1023
            {   // A: K-major, 128B rows, SW128
                const int r = G >> 3, g = G & 7;
                const uint32_t d = (uint32_t)(r * 128 + ((g ^ (r & 7)) * 16));
                const size_t o = (size_t)(bm + r) * Kdim + k0 + g * 8;
                cp_async16(base + d, Ah + o);
            }
            if (BT) {
                const int r = G >> 3, g = G & 7;
                const uint32_t d = (uint32_t)(r * 128 + ((g ^ (r & 7)) * 16));
                const size_t o = (size_t)(bn + r) * Kdim + k0 + g * 8;
                cp_async16(base + OFF_B + d, Bh + o);
            } else {
                const int r = G >> 4, c = G & 15;   // 64 rows x 16 granules
                const uint32_t d = (uint32_t)(r * 272 + c * 16);
                const size_t o = (size_t)(k0 + r) * Ncols + bn + c * 8;
                cp_async16(base + OFF_B + d, Bh + o);
            }
        }
        cp_commit();
    };

    load_stage(0, 0);
    if (nk > 1) load_stage(1, 1);

    for (int i = 0; i < nk; i++) {
        const int st = i % 3;
        if (i + 1 < nk) cp_wait<1>();
        else            cp_wait<0>();
        __syncthreads();
        if (i + 2 < nk) load_stage((i + 2) % 3, i + 2);

        const uint32_t base = smb + (uint32_t)st * STB;

#pragma unroll
        for (int ks = 0; ks < 4; ks++) {
            const uint32_t gbase = (uint32_t)(ks * 2 + (lane >> 4));  // granule 0..7

            uint32_t fah[4][4];
#pragma unroll
            for (int mi = 0; mi < 4; mi++) {
                const uint32_t d = rowa[mi] + ((gbase ^ swza[mi]) * 16);
                ldsm_x4(fah[mi][0], fah[mi][1], fah[mi][2], fah[mi][3], base + d);
            }
            uint32_t fbh[4][2];
#pragma unroll
            for (int nb = 0; nb < 2; nb++) {
                uint32_t r0, r1, r2, r3;
                if (BT) {
                    const uint32_t d = rowb[nb] + ((gbase ^ swzb[nb]) * 16);
                    ldsm_x4(r0, r1, r2, r3, base + OFF_B + d);
                    fbh[2 * nb][0] = r0; fbh[2 * nb][1] = r2;
                    fbh[2 * nb + 1][0] = r1; fbh[2 * nb + 1][1] = r3;
                } else {
                    const uint32_t d = offbt[nb] + (uint32_t)(ks * 16 * 272);
                    ldsm_x4_t(r0, r1, r2, r3, base + OFF_B + d);
                    fbh[2 * nb][0] = r0; fbh[2 * nb][1] = r1;
                    fbh[2 * nb + 1][0] = r2; fbh[2 * nb + 1][1] = r3;
                }
            }
#pragma unroll
            for (int mi = 0; mi < 4; mi++)
#pragma unroll
                for (int ni = 0; ni < 4; ni++)
                    mma16816(acc[mi][ni], fah[mi], fbh[ni]);
        }
    }

    // ---- epilogue
#pragma unroll
    for (int mi = 0; mi < 4; mi++) {
#pragma unroll
        for (int ni = 0; ni < 4; ni++) {
#pragma unroll
            for (int h = 0; h < 2; h++) {
                const int r = bm + wm + mi * 16 + (lane >> 2) + h * 8;
                const int c = bn + wn + ni * 8 + ((lane & 3) << 1);
                float v0 = acc[mi][ni][2 * h + 0] * alpha;
                float v1 = acc[mi][ni][2 * h + 1] * alpha;
                if (HAS_BIAS) { v0 += bias[c]; v1 += bias[c + 1]; }
                const size_t idx = (size_t)r * Ncols + c;
                if (WF32) {
                    float2 o; o.x = v0; o.y = v1;
                    *(float2*)(Cf + idx) = o;
                }
                if (WF16) {
                    *(__half2*)(Ch + idx) =
                        __halves2half2(__float2half(v0), __float2half(v1));
                }
            }
        }
    }
}

// ---------------------------------------------------------------------------
// Row softmax over fp32 S; emits fp16 probabilities.
// ---------------------------------------------------------------------------
__global__ __launch_bounds__(256)
void softmax_h(const float* __restrict__ S, __half* __restrict__ Sh) {
    constexpr int T = 256;
    constexpr int VPT = N_TOK / T;  // 16
    const int row = blockIdx.x;
    const int tid = threadIdx.x;
    const float* p = S + (size_t)row * N_TOK;

    float v[VPT];
    float m = -3.0e38f;
#pragma unroll
    for (int i = 0; i < VPT; i++) {
        v[i] = p[tid + i * T];
        m = fmaxf(m, v[i]);
    }
    __shared__ float red[T];
    red[tid] = m;
    __syncthreads();
    for (int s = T / 2; s > 0; s >>= 1) {
        if (tid < s) red[tid] = fmaxf(red[tid], red[tid + s]);
        __syncthreads();
    }
    m = red[0];
    __syncthreads();

    float sum = 0.f;
#pragma unroll
    for (int i = 0; i < VPT; i++) {
        v[i] = __expf(v[i] - m);
        sum += v[i];
    }
    red[tid] = sum;
    __syncthreads();
    for (int s = T / 2; s > 0; s >>= 1) {
        if (tid < s) red[tid] += red[tid + s];
        __syncthreads();
    }
    const float inv = 1.f / red[0];
#pragma unroll
    for (int i = 0; i < VPT; i++)
        Sh[(size_t)row * N_TOK + tid + i * T] = __float2half(v[i] * inv);
}

// ---------------------------------------------------------------------------
// Launch
// ---------------------------------------------------------------------------
extern "C" void kernel_launch(void* const* d_in, const int* in_sizes, int n_in,
                              void* d_out, int out_size) {
    const float* x  = (const float*)d_in[0];
    const float* W1 = (const float*)d_in[1];
    const float* b1 = (const float*)d_in[2];
    const float* W2 = (const float*)d_in[3];
    const float* b2 = (const float*)d_in[4];
    const float* W3 = (const float*)d_in[5];
    const float* b3 = (const float*)d_in[6];
    float* out = (float*)d_out;

    __half *xh, *w1h, *w2h, *w3h, *qh, *kh, *vh, *sh;
    float* S;
    cudaGetSymbolAddress((void**)&xh, g_xh);
    cudaGetSymbolAddress((void**)&w1h, g_w1h);
    cudaGetSymbolAddress((void**)&w2h, g_w2h);
    cudaGetSymbolAddress((void**)&w3h, g_w3h);
    cudaGetSymbolAddress((void**)&qh, g_qh);
    cudaGetSymbolAddress((void**)&kh, g_kh);
    cudaGetSymbolAddress((void**)&vh, g_vh);
    cudaGetSymbolAddress((void**)&sh, g_sh);
    cudaGetSymbolAddress((void**)&S, g_S);

    cudaFuncSetAttribute(mma_gemm<true, true, false, true, true>,
                         cudaFuncAttributeMaxDynamicSharedMemorySize, GM_SMEM(true));
    cudaFuncSetAttribute(mma_gemm<true, false, true, false, false>,
                         cudaFuncAttributeMaxDynamicSharedMemorySize, GM_SMEM(true));
    cudaFuncSetAttribute(mma_gemm<false, false, true, false, false>,
                         cudaFuncAttributeMaxDynamicSharedMemorySize, GM_SMEM(false));

    const dim3 blk(256);

    const int nx4 = N_TOK * D_MODEL / 4;
    const int nw4 = D_MODEL * D_MODEL / 4;
    cvt_kernel<<<(nx4 + 255) / 256, blk>>>(x, xh, nx4);
    cvt3_kernel<<<dim3((nw4 + 255) / 256, 3), blk>>>(W1, w1h, W2, w2h, W3, w3h, nw4);

    const dim3 grid_qkv(D_MODEL / 128, N_TOK / 128, 3);  // (8, 32, 3)
    const dim3 grid_attn(N_TOK / 128, N_TOK / 128);      // (32, 32)
    const dim3 grid_pv(D_MODEL / 128, N_TOK / 128);      // (8, 32)

    // merged Q/K/V projections (fp16 out, +bias)
    mma_gemm<true, true, false, true, true><<<grid_qkv, blk, GM_SMEM(true)>>>(
        xh, w1h, w2h, w3h, b1, b2, b3,
        nullptr, qh, kh, vh, N_TOK, D_MODEL, D_MODEL, 1.f);

    // S = scale * K @ Q^T  (fp32 out)
    const float scale = rsqrtf((float)D_MODEL);
    mma_gemm<true, false, true, false, false><<<grid_attn, blk, GM_SMEM(true)>>>(
        kh, qh, nullptr, nullptr, nullptr, nullptr, nullptr,
        S, nullptr, nullptr, nullptr, N_TOK, N_TOK, D_MODEL, scale);

    // softmax rows -> fp16 probabilities
    softmax_h<<<N_TOK, blk>>>(S, sh);

    // out = P @ V (fp32 out)
    mma_gemm<false, false, true, false, false><<<grid_pv, blk, GM_SMEM(false)>>>(
        sh, vh, nullptr, nullptr, nullptr, nullptr, nullptr,
        out, nullptr, nullptr, nullptr, N_TOK, D_MODEL, N_TOK, 1.f);
}